// round 6
// baseline (speedup 1.0000x reference)
#include <cuda_runtime.h>
#include <cuda_fp16.h>
#include <mma.h>

using namespace nvcuda;

// Problem dims
#define T_STEPS 32
#define BATCH   64
#define SRC     64
#define HID     1024
#define EMBD    512

// Output layout (flattened pytree: outputs, h_T, c_T, attn_std, attn_copy)
#define OUT_H     2097152   // h_T offset (after outputs T*B*H)
#define OUT_C     2228224
#define OUT_ASTD  2359296
#define OUT_ACOPY 2490368

// ---------------------------------------------------------------------------
// Device scratch (static; no allocations allowed). 256B-aligned: the GEMM
// loaders use int4 (16B) vector accesses.
// ---------------------------------------------------------------------------
__device__ __align__(256) __half g_Wcat0[4096 * 2560];     // layer0 [W_ih0|W_hh0], rows h*4+gate
__device__ __align__(256) __half g_Wcat1[4096 * 2048];     // layer1 [W_ih1|W_hh1], reordered
__device__ __align__(256) __half g_Wao[1024 * 2048];       // attn_out_w fp16
__device__ __align__(256) __half g_attn_inT[1024 * 1024];  // attn_in_w^T fp16
__device__ __align__(256) __half g_copy_inT[1024 * 1024];  // copy_in_w^T fp16
__device__ __align__(256) __half g_ctxh[BATCH * SRC * HID];   // ctx (B,S,H) fp16
__device__ __align__(256) float  g_ctxA[BATCH * SRC * HID];   // ctx @ attn_in  (fp32)
__device__ __align__(256) float  g_ctxC[BATCH * SRC * HID];   // ctx @ copy_in  (fp32)
__device__ __align__(256) __half g_embAll[T_STEPS * BATCH * EMBD];
__device__ __align__(256) __half g_x0[BATCH * 2560];       // [emb | feed | h0prev]
__device__ __align__(256) __half g_x1a[BATCH * 2048];      // [h0_new | h1_prev] ping
__device__ __align__(256) __half g_x1b[BATCH * 2048];      // pong
__device__ __align__(256) __half g_xattn[BATCH * 2048];    // [wctx | h1_new]
__device__ __align__(256) __half g_outf16[BATCH * HID];    // attention output fp16

// ---------------------------------------------------------------------------
// Setup / conversion kernels
// ---------------------------------------------------------------------------
__global__ void k_conv_gates(const float* __restrict__ Wih, const float* __restrict__ Whh,
                             __half* __restrict__ dst, int Kih, int Kt) {
    int total = 4096 * Kt;
    for (int idx = blockIdx.x * blockDim.x + threadIdx.x; idx < total;
         idx += gridDim.x * blockDim.x) {
        int r = idx / Kt, k = idx - r * Kt;
        int h = r >> 2, g = r & 3;
        int sr = g * 1024 + h;
        float v = (k < Kih) ? Wih[(size_t)sr * Kih + k] : Whh[(size_t)sr * 1024 + (k - Kih)];
        dst[idx] = __float2half(v);
    }
}

__global__ void k_conv_plain(const float* __restrict__ src, __half* __restrict__ dst, int n) {
    for (int i = blockIdx.x * blockDim.x + threadIdx.x; i < n; i += gridDim.x * blockDim.x)
        dst[i] = __float2half(src[i]);
}

__global__ void k_conv_T(const float* __restrict__ src, __half* __restrict__ dst) {
    // dst[e][d] = src[d][e], 1024x1024
    for (int i = blockIdx.x * blockDim.x + threadIdx.x; i < 1024 * 1024;
         i += gridDim.x * blockDim.x) {
        int e = i >> 10, d = i & 1023;
        dst[i] = __float2half(src[d * 1024 + e]);
    }
}

__global__ void k_conv_ctx(const float* __restrict__ context, __half* __restrict__ dst) {
    // ctxh[b][s][h] = context[s][b][h]
    for (int i = blockIdx.x * blockDim.x + threadIdx.x; i < BATCH * SRC * HID;
         i += gridDim.x * blockDim.x) {
        int b = i >> 16;
        int rest = i & 65535;
        int s = rest >> 10, h = rest & 1023;
        dst[i] = __float2half(context[((size_t)s * BATCH + b) * HID + h]);
    }
}

__global__ void k_emb_all(const int* __restrict__ input, const float* __restrict__ emb,
                          __half* __restrict__ dst) {
    for (int i = blockIdx.x * blockDim.x + threadIdx.x; i < T_STEPS * BATCH * EMBD;
         i += gridDim.x * blockDim.x) {
        int e = i & (EMBD - 1);
        int tb = i >> 9;          // t*B + b
        int id = input[tb];
        dst[i] = __float2half(emb[(size_t)id * EMBD + e]);
    }
}

__global__ void k_copy_c(const float* __restrict__ c0, float* __restrict__ dst) {
    for (int i = blockIdx.x * blockDim.x + threadIdx.x; i < 2 * BATCH * HID;
         i += gridDim.x * blockDim.x)
        dst[i] = c0[i];
}

__global__ void k_init(const int* __restrict__ input, const float* __restrict__ emb,
                       const float* __restrict__ init_output, const float* __restrict__ h0,
                       __half* __restrict__ x0, __half* __restrict__ x1a) {
    int b = blockIdx.x, tid = threadIdx.x;
    int id = input[b];  // t = 0
    for (int e = tid; e < EMBD; e += 256)
        x0[b * 2560 + e] = __float2half(emb[(size_t)id * EMBD + e]);
    for (int j = tid; j < HID; j += 256) {
        x0[b * 2560 + 512 + j]  = __float2half(init_output[b * HID + j]);
        x0[b * 2560 + 1536 + j] = __float2half(h0[b * HID + j]);                 // layer0 h
        x1a[b * 2048 + 1024 + j] = __float2half(h0[BATCH * HID + b * HID + j]);  // layer1 h
    }
}

// ---------------------------------------------------------------------------
// GEMM: C[m][n] = sum_k A[m][k] * B[n][k]   (A: 64xK fp16 rowmajor, B: NxK fp16 rowmajor)
// Software-pipelined double-buffered smem (register-staged LDG -> MMA -> STS).
// MODE 0: LSTM gates (weight rows are h*4+gate) + fused pointwise epilogue
// MODE 1: tanh epilogue, dual fp32+fp16 store (attention output)
// MODE 2: fp32 store (ctxA/ctxC precompute), M-tiled via blockIdx.y
// ---------------------------------------------------------------------------
template <int BN, int MODE>
__global__ void __launch_bounds__(256) gemm_kernel(
    const __half* __restrict__ A, int lda,
    const __half* __restrict__ B, int ldb, int K,
    const float* __restrict__ bias,
    float* __restrict__ c_state, float* __restrict__ h32,
    __half* __restrict__ hf16a, __half* __restrict__ hf16b,
    float* __restrict__ out32, __half* __restrict__ out16)
{
    constexpr int LDS  = 72;
    constexpr int PADC = BN + 8;
    constexpr int TILE = (64 + BN) * LDS;           // halves per buffer
    constexpr int SZ_AB = 2 * TILE * 2;             // two buffers, 2B each
    constexpr int SZ_C  = 64 * PADC * 4;
    constexpr int SMEMSZ = (SZ_AB > SZ_C) ? SZ_AB : SZ_C;
    __shared__ __align__(32) char smbuf[SMEMSZ];
    __half* As0 = (__half*)smbuf;
    __half* Bs0 = As0 + 64 * LDS;
    __half* As1 = As0 + TILE;
    __half* Bs1 = Bs0 + TILE;
    float*  Cs = (float*)smbuf;

    const int tid = threadIdx.x;
    const int wid = tid >> 5;
    const int n0 = blockIdx.x * BN;
    const int m0 = blockIdx.y * 64;
    const __half* Ab = A + (size_t)m0 * lda;
    const __half* Bb = B + (size_t)n0 * ldb;

    const int wm = wid >> 1;  // 0..3
    const int wn = wid & 1;   // 0..1
    constexpr int NT = (BN / 2) / 16;  // accum tiles per warp along N
    constexpr int BT = BN / 32;        // B-loader iterations

    wmma::fragment<wmma::accumulator, 16, 16, 16, float> acc[NT];
#pragma unroll
    for (int i = 0; i < NT; i++) wmma::fill_fragment(acc[i], 0.f);

    int4 ra[2], rb[BT];

    // Prologue: chunk 0 -> buffer 0
#pragma unroll
    for (int t = 0; t < 2; t++) {
        int i = tid + t * 256;
        ra[t] = *(const int4*)(Ab + (size_t)(i >> 3) * lda + (i & 7) * 8);
    }
#pragma unroll
    for (int t = 0; t < BT; t++) {
        int i = tid + t * 256;
        rb[t] = *(const int4*)(Bb + (size_t)(i >> 3) * ldb + (i & 7) * 8);
    }
#pragma unroll
    for (int t = 0; t < 2; t++) {
        int i = tid + t * 256;
        *(int4*)(As0 + (i >> 3) * LDS + (i & 7) * 8) = ra[t];
    }
#pragma unroll
    for (int t = 0; t < BT; t++) {
        int i = tid + t * 256;
        *(int4*)(Bs0 + (i >> 3) * LDS + (i & 7) * 8) = rb[t];
    }
    __syncthreads();

    const int nChunks = K >> 6;
    for (int kc = 0; kc < nChunks; kc++) {
        const __half* Ac = (kc & 1) ? As1 : As0;
        const __half* Bc = (kc & 1) ? Bs1 : Bs0;
        __half* An = (kc & 1) ? As0 : As1;
        __half* Bn = (kc & 1) ? Bs0 : Bs1;
        const bool has_next = (kc + 1) < nChunks;

        if (has_next) {
            int kcol = (kc + 1) << 6;
#pragma unroll
            for (int t = 0; t < 2; t++) {
                int i = tid + t * 256;
                ra[t] = *(const int4*)(Ab + (size_t)(i >> 3) * lda + kcol + (i & 7) * 8);
            }
#pragma unroll
            for (int t = 0; t < BT; t++) {
                int i = tid + t * 256;
                rb[t] = *(const int4*)(Bb + (size_t)(i >> 3) * ldb + kcol + (i & 7) * 8);
            }
        }

#pragma unroll
        for (int kk = 0; kk < 4; kk++) {
            wmma::fragment<wmma::matrix_a, 16, 16, 16, __half, wmma::row_major> af;
            wmma::load_matrix_sync(af, Ac + (wm * 16) * LDS + kk * 16, LDS);
#pragma unroll
            for (int nt = 0; nt < NT; nt++) {
                wmma::fragment<wmma::matrix_b, 16, 16, 16, __half, wmma::col_major> bf;
                wmma::load_matrix_sync(bf, Bc + (wn * (BN / 2) + nt * 16) * LDS + kk * 16, LDS);
                wmma::mma_sync(acc[nt], af, bf, acc[nt]);
            }
        }

        if (has_next) {
#pragma unroll
            for (int t = 0; t < 2; t++) {
                int i = tid + t * 256;
                *(int4*)(An + (i >> 3) * LDS + (i & 7) * 8) = ra[t];
            }
#pragma unroll
            for (int t = 0; t < BT; t++) {
                int i = tid + t * 256;
                *(int4*)(Bn + (i >> 3) * LDS + (i & 7) * 8) = rb[t];
            }
        }
        __syncthreads();
    }

#pragma unroll
    for (int nt = 0; nt < NT; nt++)
        wmma::store_matrix_sync(Cs + (wm * 16) * PADC + wn * (BN / 2) + nt * 16, acc[nt],
                                PADC, wmma::mem_row_major);
    __syncthreads();

    if constexpr (MODE == 0) {
        constexpr int JH = BN / 4;
        for (int ei = tid; ei < 64 * JH; ei += 256) {
            int b = ei / JH, jl = ei % JH;
            int h = (n0 >> 2) + jl;
            float gi = Cs[b * PADC + 4 * jl + 0] + bias[h];
            float gf = Cs[b * PADC + 4 * jl + 1] + bias[1024 + h];
            float gg = Cs[b * PADC + 4 * jl + 2] + bias[2048 + h];
            float go = Cs[b * PADC + 4 * jl + 3] + bias[3072 + h];
            float co = c_state[b * HID + h];
            float si = 1.f / (1.f + expf(-gi));
            float sf = 1.f / (1.f + expf(-gf));
            float so = 1.f / (1.f + expf(-go));
            float cn = sf * co + si * tanhf(gg);
            float hn = so * tanhf(cn);
            c_state[b * HID + h] = cn;
            h32[b * HID + h] = hn;
            __half hh = __float2half(hn);
            hf16a[b * 2048 + h] = hh;
            if (hf16b) hf16b[b * 2048 + h] = hh;
        }
    } else if constexpr (MODE == 1) {
        for (int ei = tid; ei < 64 * BN; ei += 256) {
            int b = ei / BN, n = ei % BN;
            float v = tanhf(Cs[b * PADC + n]);
            int col = n0 + n;
            out32[b * HID + col] = v;
            out16[b * HID + col] = __float2half(v);
        }
    } else {
        for (int ei = tid; ei < 64 * BN; ei += 256) {
            int b = ei / BN, n = ei % BN;
            out32[(size_t)(m0 + b) * HID + n0 + n] = Cs[b * PADC + n];
        }
    }
}

// ---------------------------------------------------------------------------
// Attention (one block per batch row, 512 threads). Scores/softmax fully fp32.
// ---------------------------------------------------------------------------
__global__ void __launch_bounds__(512) attn_std_kernel(
    const float* __restrict__ q32,    // h_T layer1 slot (B,H) fp32, updated this step
    const float* __restrict__ ctxA,   // (B,S,H) fp32
    const __half* __restrict__ ctxh,  // (B,S,H) fp16
    float* __restrict__ astd,         // + t*B*S
    __half* __restrict__ wctx)        // xattn, stride 2048
{
    int b = blockIdx.x, tid = threadIdx.x, lane = tid & 31, wid = tid >> 5;
    __shared__ float sc[64];
    __shared__ __align__(16) float qs[1024];
    const float4* qrow = (const float4*)(q32 + (size_t)b * HID);
    for (int i = tid; i < 256; i += 512) *(float4*)(qs + 4 * i) = qrow[i];
    __syncthreads();

    for (int s = wid; s < 64; s += 16) {
        const float4* crow = (const float4*)(ctxA + ((size_t)((b << 6) + s)) * HID);
        float acc = 0.f;
#pragma unroll 2
        for (int e = lane; e < 256; e += 32) {
            float4 a = crow[e];
            float4 qv = *(const float4*)(qs + 4 * e);
            acc += a.x * qv.x + a.y * qv.y + a.z * qv.z + a.w * qv.w;
        }
        for (int o = 16; o; o >>= 1) acc += __shfl_xor_sync(0xffffffffu, acc, o);
        if (!lane) sc[s] = acc;
    }
    __syncthreads();
    if (tid < 32) {
        float s0 = sc[tid], s1 = sc[tid + 32];
        float m = fmaxf(s0, s1);
        for (int o = 16; o; o >>= 1) m = fmaxf(m, __shfl_xor_sync(0xffffffffu, m, o));
        float e0 = expf(s0 - m), e1 = expf(s1 - m);
        float sum = e0 + e1;
        for (int o = 16; o; o >>= 1) sum += __shfl_xor_sync(0xffffffffu, sum, o);
        float inv = 1.f / sum;
        float p0 = e0 * inv, p1 = e1 * inv;
        sc[tid] = p0; sc[tid + 32] = p1;
        astd[(b << 6) + tid] = p0;
        astd[(b << 6) + tid + 32] = p1;
    }
    __syncthreads();
    const __half2* cb = (const __half2*)(ctxh + (size_t)b * 65536);
    __half2* wrow = (__half2*)(wctx + b * 2048);
    for (int e = tid; e < 512; e += 512) {
        float ax = 0.f, ay = 0.f;
#pragma unroll 8
        for (int s = 0; s < 64; s++) {
            float p = sc[s];
            float2 v = __half22float2(cb[s * 512 + e]);
            ax += p * v.x; ay += p * v.y;
        }
        wrow[e] = __floats2half2_rn(ax, ay);
    }
}

__global__ void __launch_bounds__(512) attn_copy_kernel(
    const float* __restrict__ q32,    // outputs[t] slot (B,H) fp32
    const float* __restrict__ ctxC,   // (B,S,H) fp32
    float* __restrict__ acopy,        // + t*B*S
    const __half* __restrict__ o16,   // attention out fp16, stride 1024
    const __half* __restrict__ embT,  // embAll + tn*B*E
    const __half* __restrict__ h0f,   // x1cur, stride 2048, offset 0
    __half* __restrict__ x0)
{
    int b = blockIdx.x, tid = threadIdx.x, lane = tid & 31, wid = tid >> 5;
    __shared__ float sc[64];
    __shared__ __align__(16) float qs[1024];
    const float4* qrow = (const float4*)(q32 + (size_t)b * HID);
    for (int i = tid; i < 256; i += 512) *(float4*)(qs + 4 * i) = qrow[i];
    __syncthreads();

    for (int s = wid; s < 64; s += 16) {
        const float4* crow = (const float4*)(ctxC + ((size_t)((b << 6) + s)) * HID);
        float acc = 0.f;
#pragma unroll 2
        for (int e = lane; e < 256; e += 32) {
            float4 a = crow[e];
            float4 qv = *(const float4*)(qs + 4 * e);
            acc += a.x * qv.x + a.y * qv.y + a.z * qv.z + a.w * qv.w;
        }
        for (int o = 16; o; o >>= 1) acc += __shfl_xor_sync(0xffffffffu, acc, o);
        if (!lane) sc[s] = acc;
    }
    __syncthreads();
    if (tid < 32) {
        float s0 = sc[tid], s1 = sc[tid + 32];
        float m = fmaxf(s0, s1);
        for (int o = 16; o; o >>= 1) m = fmaxf(m, __shfl_xor_sync(0xffffffffu, m, o));
        float e0 = expf(s0 - m), e1 = expf(s1 - m);
        float sum = e0 + e1;
        for (int o = 16; o; o >>= 1) sum += __shfl_xor_sync(0xffffffffu, sum, o);
        float inv = 1.f / sum;
        acopy[(b << 6) + tid] = e0 * inv;
        acopy[(b << 6) + tid + 32] = e1 * inv;
    }
    // build next step's x0 = [emb(t+1) | out_feed | h0_new]
    __half2* xr = (__half2*)(x0 + b * 2560);
    const __half2* er = (const __half2*)(embT + b * EMBD);
    for (int i = tid; i < 256; i += 512) xr[i] = er[i];
    for (int i = tid; i < 512; i += 512) {
        xr[256 + i] = ((const __half2*)(o16 + b * 1024))[i];
        xr[768 + i] = ((const __half2*)(h0f + b * 2048))[i];
    }
}

// ---------------------------------------------------------------------------
// Launch
// ---------------------------------------------------------------------------
extern "C" void kernel_launch(void* const* d_in, const int* in_sizes, int n_in,
                              void* d_out, int out_size) {
    const int*   input   = (const int*)d_in[0];
    const float* h0      = (const float*)d_in[1];
    const float* c0      = (const float*)d_in[2];
    const float* context = (const float*)d_in[3];
    const float* init_o  = (const float*)d_in[4];
    const float* emb     = (const float*)d_in[5];
    const float* Wih0    = (const float*)d_in[6];
    const float* Whh0    = (const float*)d_in[7];
    const float* b0      = (const float*)d_in[8];
    const float* Wih1    = (const float*)d_in[9];
    const float* Whh1    = (const float*)d_in[10];
    const float* b1      = (const float*)d_in[11];
    const float* ain     = (const float*)d_in[12];
    const float* aout    = (const float*)d_in[13];
    const float* cin     = (const float*)d_in[14];
    float* out = (float*)d_out;

    __half *Wcat0, *Wcat1, *Wao, *ainT, *cinT, *ctxh, *embA;
    float *ctxA, *ctxC;
    __half *x0, *x1a, *x1b, *xattn, *o16;
    cudaGetSymbolAddress((void**)&Wcat0, g_Wcat0);
    cudaGetSymbolAddress((void**)&Wcat1, g_Wcat1);
    cudaGetSymbolAddress((void**)&Wao, g_Wao);
    cudaGetSymbolAddress((void**)&ainT, g_attn_inT);
    cudaGetSymbolAddress((void**)&cinT, g_copy_inT);
    cudaGetSymbolAddress((void**)&ctxh, g_ctxh);
    cudaGetSymbolAddress((void**)&ctxA, g_ctxA);
    cudaGetSymbolAddress((void**)&ctxC, g_ctxC);
    cudaGetSymbolAddress((void**)&embA, g_embAll);
    cudaGetSymbolAddress((void**)&x0, g_x0);
    cudaGetSymbolAddress((void**)&x1a, g_x1a);
    cudaGetSymbolAddress((void**)&x1b, g_x1b);
    cudaGetSymbolAddress((void**)&xattn, g_xattn);
    cudaGetSymbolAddress((void**)&o16, g_outf16);

    // One-time (per replay) conversions
    k_conv_gates<<<2048, 256>>>(Wih0, Whh0, Wcat0, 1536, 2560);
    k_conv_gates<<<2048, 256>>>(Wih1, Whh1, Wcat1, 1024, 2048);
    k_conv_plain<<<1024, 256>>>(aout, Wao, 1024 * 2048);
    k_conv_T<<<512, 256>>>(ain, ainT);
    k_conv_T<<<512, 256>>>(cin, cinT);
    k_conv_ctx<<<2048, 256>>>(context, ctxh);
    k_emb_all<<<512, 256>>>(input, emb, embA);
    k_copy_c<<<256, 256>>>(c0, out + OUT_C);
    k_init<<<64, 256>>>(input, emb, init_o, h0, x0, x1a);

    // ctxA = ctx @ attn_in, ctxC = ctx @ copy_in  (fp32 out)
    gemm_kernel<64, 2><<<dim3(16, 64), 256>>>(ctxh, 1024, ainT, 1024, 1024,
        nullptr, nullptr, nullptr, nullptr, nullptr, ctxA, nullptr);
    gemm_kernel<64, 2><<<dim3(16, 64), 256>>>(ctxh, 1024, cinT, 1024, 1024,
        nullptr, nullptr, nullptr, nullptr, nullptr, ctxC, nullptr);

    for (int t = 0; t < T_STEPS; t++) {
        __half* x1cur = (t & 1) ? x1b : x1a;
        __half* x1nxt = (t & 1) ? x1a : x1b;

        // Layer 0 gates + LSTM pointwise (h0_new -> x1cur[:,0:1024])
        gemm_kernel<64, 0><<<dim3(64, 1), 256>>>(x0, 2560, Wcat0, 2560, 2560,
            b0, out + OUT_C, out + OUT_H, x1cur, nullptr, nullptr, nullptr);

        // Layer 1 gates + pointwise (h1_new -> xattn[:,1024:], x1nxt[:,1024:], h_T[1] fp32)
        gemm_kernel<64, 0><<<dim3(64, 1), 256>>>(x1cur, 2048, Wcat1, 2048, 2048,
            b1, out + OUT_C + BATCH * HID, out + OUT_H + BATCH * HID,
            xattn + 1024, x1nxt + 1024, nullptr, nullptr);

        // Standard attention: fp32 scores(h1, ctxA) -> softmax -> attn_std, wctx
        attn_std_kernel<<<64, 512>>>(out + OUT_H + BATCH * HID, ctxA, ctxh,
            out + OUT_ASTD + t * BATCH * SRC, xattn);

        // out = tanh([wctx|h1] @ attn_out^T)  (fp32 -> outputs[t], fp16 -> o16)
        gemm_kernel<32, 1><<<dim3(32, 1), 256>>>(xattn, 2048, Wao, 2048, 2048,
            nullptr, nullptr, nullptr, nullptr, nullptr,
            out + (size_t)t * BATCH * HID, o16);

        // Copy attention (fp32 scores) + build x0 for next step
        int tn = (t + 1 < T_STEPS) ? t + 1 : T_STEPS - 1;
        attn_copy_kernel<<<64, 512>>>(out + (size_t)t * BATCH * HID, ctxC,
            out + OUT_ACOPY + t * BATCH * SRC,
            o16, embA + (size_t)tn * BATCH * EMBD, x1cur, x0);
    }
}

// round 8
// speedup vs baseline: 1.1424x; 1.1424x over previous
#include <cuda_runtime.h>
#include <cuda_fp16.h>
#include <mma.h>

using namespace nvcuda;

// Problem dims
#define T_STEPS 32
#define BATCH   64
#define SRC     64
#define HID     1024
#define EMBD    512

// Output layout (flattened pytree: outputs, h_T, c_T, attn_std, attn_copy)
#define OUT_H     2097152   // h_T offset (after outputs T*B*H)
#define OUT_C     2228224
#define OUT_ASTD  2359296
#define OUT_ACOPY 2490368

// ---------------------------------------------------------------------------
// Device scratch (static; no allocations allowed). 256B-aligned (int4 loads).
// ---------------------------------------------------------------------------
__device__ __align__(256) __half g_Wcat0[4096 * 2560];     // layer0 [W_ih0|W_hh0], rows h*4+gate
__device__ __align__(256) __half g_Wcat1[4096 * 2048];     // layer1 [W_ih1|W_hh1], reordered
__device__ __align__(256) __half g_Wao[1024 * 2048];       // attn_out_w fp16
__device__ __align__(256) __half g_attn_inT[1024 * 1024];  // attn_in_w^T fp16
__device__ __align__(256) __half g_copy_inT[1024 * 1024];  // copy_in_w^T fp16
__device__ __align__(256) __half g_ctxh[BATCH * SRC * HID];   // ctx (B,S,H) fp16
__device__ __align__(256) float  g_ctxA[BATCH * SRC * HID];   // ctx @ attn_in  (fp32)
__device__ __align__(256) float  g_ctxC[BATCH * SRC * HID];   // ctx @ copy_in  (fp32)
__device__ __align__(256) __half g_embAll[T_STEPS * BATCH * EMBD];
__device__ __align__(256) __half g_x0[BATCH * 2560];       // [emb | feed | h0prev]
__device__ __align__(256) __half g_x1a[BATCH * 2048];      // [h0_new | h1_prev] ping
__device__ __align__(256) __half g_x1b[BATCH * 2048];      // pong
__device__ __align__(256) __half g_xattn[BATCH * 2048];    // [wctx | h1_new]
__device__ __align__(256) __half g_outf16[BATCH * HID];    // attention output fp16
__device__ __align__(256) float  g_projpart[2 * BATCH * HID]; // split-K partials (proj)

// ---------------------------------------------------------------------------
// Setup / conversion kernels
// ---------------------------------------------------------------------------
__global__ void k_conv_gates(const float* __restrict__ Wih, const float* __restrict__ Whh,
                             __half* __restrict__ dst, int Kih, int Kt) {
    int total = 4096 * Kt;
    for (int idx = blockIdx.x * blockDim.x + threadIdx.x; idx < total;
         idx += gridDim.x * blockDim.x) {
        int r = idx / Kt, k = idx - r * Kt;
        int h = r >> 2, g = r & 3;
        int sr = g * 1024 + h;
        float v = (k < Kih) ? Wih[(size_t)sr * Kih + k] : Whh[(size_t)sr * 1024 + (k - Kih)];
        dst[idx] = __float2half(v);
    }
}

__global__ void k_conv_plain(const float* __restrict__ src, __half* __restrict__ dst, int n) {
    for (int i = blockIdx.x * blockDim.x + threadIdx.x; i < n; i += gridDim.x * blockDim.x)
        dst[i] = __float2half(src[i]);
}

__global__ void k_conv_T(const float* __restrict__ src, __half* __restrict__ dst) {
    // dst[e][d] = src[d][e], 1024x1024
    for (int i = blockIdx.x * blockDim.x + threadIdx.x; i < 1024 * 1024;
         i += gridDim.x * blockDim.x) {
        int e = i >> 10, d = i & 1023;
        dst[i] = __float2half(src[d * 1024 + e]);
    }
}

__global__ void k_conv_ctx(const float* __restrict__ context, __half* __restrict__ dst) {
    // ctxh[b][s][h] = context[s][b][h]
    for (int i = blockIdx.x * blockDim.x + threadIdx.x; i < BATCH * SRC * HID;
         i += gridDim.x * blockDim.x) {
        int b = i >> 16;
        int rest = i & 65535;
        int s = rest >> 10, h = rest & 1023;
        dst[i] = __float2half(context[((size_t)s * BATCH + b) * HID + h]);
    }
}

__global__ void k_emb_all(const int* __restrict__ input, const float* __restrict__ emb,
                          __half* __restrict__ dst) {
    for (int i = blockIdx.x * blockDim.x + threadIdx.x; i < T_STEPS * BATCH * EMBD;
         i += gridDim.x * blockDim.x) {
        int e = i & (EMBD - 1);
        int tb = i >> 9;          // t*B + b
        int id = input[tb];
        dst[i] = __float2half(emb[(size_t)id * EMBD + e]);
    }
}

__global__ void k_copy_c(const float* __restrict__ c0, float* __restrict__ dst) {
    for (int i = blockIdx.x * blockDim.x + threadIdx.x; i < 2 * BATCH * HID;
         i += gridDim.x * blockDim.x)
        dst[i] = c0[i];
}

__global__ void k_init(const int* __restrict__ input, const float* __restrict__ emb,
                       const float* __restrict__ init_output, const float* __restrict__ h0,
                       __half* __restrict__ x0, __half* __restrict__ x1a) {
    int b = blockIdx.x, tid = threadIdx.x;
    int id = input[b];  // t = 0
    for (int e = tid; e < EMBD; e += 256)
        x0[b * 2560 + e] = __float2half(emb[(size_t)id * EMBD + e]);
    for (int j = tid; j < HID; j += 256) {
        x0[b * 2560 + 512 + j]  = __float2half(init_output[b * HID + j]);
        x0[b * 2560 + 1536 + j] = __float2half(h0[b * HID + j]);                 // layer0 h
        x1a[b * 2048 + 1024 + j] = __float2half(h0[BATCH * HID + b * HID + j]);  // layer1 h
    }
}

// Split-K epilogue for the out-projection: tanh(p0+p1) -> fp32 + fp16
__global__ void k_proj_epi(const float* __restrict__ part,
                           float* __restrict__ out32, __half* __restrict__ o16) {
    int i = blockIdx.x * blockDim.x + threadIdx.x;   // 0..65535
    float v = tanhf(part[i] + part[BATCH * HID + i]);
    out32[i] = v;
    o16[i] = __float2half(v);
}

// ---------------------------------------------------------------------------
// GEMM: C[m][n] = sum_k A[m][k] * B[n][k]   (A: 64xK fp16 rowmajor, B: NxK fp16 rowmajor)
// Software-pipelined double-buffered smem (register-staged LDG -> MMA -> STS).
// MODE 0: LSTM gates (weight rows are h*4+gate) + fused pointwise epilogue
// MODE 2: fp32 store (ctxA/ctxC precompute), M-tiled via blockIdx.y
// MODE 3: split-K partial fp32 store; blockIdx.y = k-split, K = per-split length
// ---------------------------------------------------------------------------
template <int BN, int MODE>
__global__ void __launch_bounds__(256) gemm_kernel(
    const __half* __restrict__ A, int lda,
    const __half* __restrict__ B, int ldb, int K,
    const float* __restrict__ bias,
    float* __restrict__ c_state, float* __restrict__ h32,
    __half* __restrict__ hf16a, __half* __restrict__ hf16b,
    float* __restrict__ out32, __half* __restrict__ out16)
{
    constexpr int LDS  = 72;
    constexpr int PADC = BN + 8;
    constexpr int TILE = (64 + BN) * LDS;           // halves per buffer
    constexpr int SZ_AB = 2 * TILE * 2;             // two buffers, 2B each
    constexpr int SZ_C  = 64 * PADC * 4;
    constexpr int SMEMSZ = (SZ_AB > SZ_C) ? SZ_AB : SZ_C;
    __shared__ __align__(32) char smbuf[SMEMSZ];
    __half* As0 = (__half*)smbuf;
    __half* Bs0 = As0 + 64 * LDS;
    __half* As1 = As0 + TILE;
    __half* Bs1 = Bs0 + TILE;
    float*  Cs = (float*)smbuf;

    const int tid = threadIdx.x;
    const int wid = tid >> 5;
    const int n0 = blockIdx.x * BN;
    int m0 = 0, koff = 0;
    if constexpr (MODE == 2) m0 = blockIdx.y * 64;
    if constexpr (MODE == 3) koff = blockIdx.y * K;
    const __half* Ab = A + (size_t)m0 * lda + koff;
    const __half* Bb = B + (size_t)n0 * ldb + koff;

    const int wm = wid >> 1;  // 0..3
    const int wn = wid & 1;   // 0..1
    constexpr int NT = (BN / 2) / 16;  // accum tiles per warp along N
    constexpr int BT = BN / 32;        // B-loader iterations

    wmma::fragment<wmma::accumulator, 16, 16, 16, float> acc[NT];
#pragma unroll
    for (int i = 0; i < NT; i++) wmma::fill_fragment(acc[i], 0.f);

    int4 ra[2], rb[BT];

    // Prologue: chunk 0 -> buffer 0
#pragma unroll
    for (int t = 0; t < 2; t++) {
        int i = tid + t * 256;
        ra[t] = *(const int4*)(Ab + (size_t)(i >> 3) * lda + (i & 7) * 8);
    }
#pragma unroll
    for (int t = 0; t < BT; t++) {
        int i = tid + t * 256;
        rb[t] = *(const int4*)(Bb + (size_t)(i >> 3) * ldb + (i & 7) * 8);
    }
#pragma unroll
    for (int t = 0; t < 2; t++) {
        int i = tid + t * 256;
        *(int4*)(As0 + (i >> 3) * LDS + (i & 7) * 8) = ra[t];
    }
#pragma unroll
    for (int t = 0; t < BT; t++) {
        int i = tid + t * 256;
        *(int4*)(Bs0 + (i >> 3) * LDS + (i & 7) * 8) = rb[t];
    }
    __syncthreads();

    const int nChunks = K >> 6;
    for (int kc = 0; kc < nChunks; kc++) {
        const __half* Ac = (kc & 1) ? As1 : As0;
        const __half* Bc = (kc & 1) ? Bs1 : Bs0;
        __half* An = (kc & 1) ? As0 : As1;
        __half* Bn = (kc & 1) ? Bs0 : Bs1;
        const bool has_next = (kc + 1) < nChunks;

        if (has_next) {
            int kcol = (kc + 1) << 6;
#pragma unroll
            for (int t = 0; t < 2; t++) {
                int i = tid + t * 256;
                ra[t] = *(const int4*)(Ab + (size_t)(i >> 3) * lda + kcol + (i & 7) * 8);
            }
#pragma unroll
            for (int t = 0; t < BT; t++) {
                int i = tid + t * 256;
                rb[t] = *(const int4*)(Bb + (size_t)(i >> 3) * ldb + kcol + (i & 7) * 8);
            }
        }

#pragma unroll
        for (int kk = 0; kk < 4; kk++) {
            wmma::fragment<wmma::matrix_a, 16, 16, 16, __half, wmma::row_major> af;
            wmma::load_matrix_sync(af, Ac + (wm * 16) * LDS + kk * 16, LDS);
#pragma unroll
            for (int nt = 0; nt < NT; nt++) {
                wmma::fragment<wmma::matrix_b, 16, 16, 16, __half, wmma::col_major> bf;
                wmma::load_matrix_sync(bf, Bc + (wn * (BN / 2) + nt * 16) * LDS + kk * 16, LDS);
                wmma::mma_sync(acc[nt], af, bf, acc[nt]);
            }
        }

        if (has_next) {
#pragma unroll
            for (int t = 0; t < 2; t++) {
                int i = tid + t * 256;
                *(int4*)(An + (i >> 3) * LDS + (i & 7) * 8) = ra[t];
            }
#pragma unroll
            for (int t = 0; t < BT; t++) {
                int i = tid + t * 256;
                *(int4*)(Bn + (i >> 3) * LDS + (i & 7) * 8) = rb[t];
            }
        }
        __syncthreads();
    }

#pragma unroll
    for (int nt = 0; nt < NT; nt++)
        wmma::store_matrix_sync(Cs + (wm * 16) * PADC + wn * (BN / 2) + nt * 16, acc[nt],
                                PADC, wmma::mem_row_major);
    __syncthreads();

    if constexpr (MODE == 0) {
        constexpr int JH = BN / 4;
        for (int ei = tid; ei < 64 * JH; ei += 256) {
            int b = ei / JH, jl = ei % JH;
            int h = (n0 >> 2) + jl;
            float gi = Cs[b * PADC + 4 * jl + 0] + bias[h];
            float gf = Cs[b * PADC + 4 * jl + 1] + bias[1024 + h];
            float gg = Cs[b * PADC + 4 * jl + 2] + bias[2048 + h];
            float go = Cs[b * PADC + 4 * jl + 3] + bias[3072 + h];
            float co = c_state[b * HID + h];
            float si = 1.f / (1.f + expf(-gi));
            float sf = 1.f / (1.f + expf(-gf));
            float so = 1.f / (1.f + expf(-go));
            float cn = sf * co + si * tanhf(gg);
            float hn = so * tanhf(cn);
            c_state[b * HID + h] = cn;
            h32[b * HID + h] = hn;
            __half hh = __float2half(hn);
            hf16a[b * 2048 + h] = hh;
            if (hf16b) hf16b[b * 2048 + h] = hh;
        }
    } else if constexpr (MODE == 3) {
        for (int ei = tid; ei < 64 * BN; ei += 256) {
            int b = ei / BN, n = ei % BN;
            out32[((size_t)blockIdx.y * 64 + b) * HID + n0 + n] = Cs[b * PADC + n];
        }
    } else {
        for (int ei = tid; ei < 64 * BN; ei += 256) {
            int b = ei / BN, n = ei % BN;
            out32[(size_t)(m0 + b) * HID + n0 + n] = Cs[b * PADC + n];
        }
    }
}

// ---------------------------------------------------------------------------
// Attention (one block per batch row, 512 threads). Scores/softmax fully fp32.
// ---------------------------------------------------------------------------
__global__ void __launch_bounds__(512) attn_std_kernel(
    const float* __restrict__ q32,    // h_T layer1 slot (B,H) fp32, updated this step
    const float* __restrict__ ctxA,   // (B,S,H) fp32
    const __half* __restrict__ ctxh,  // (B,S,H) fp16
    float* __restrict__ astd,         // + t*B*S
    __half* __restrict__ wctx)        // xattn, stride 2048
{
    int b = blockIdx.x, tid = threadIdx.x, lane = tid & 31, wid = tid >> 5;
    __shared__ float sc[64];
    __shared__ __align__(16) float qs[1024];
    const float4* qrow = (const float4*)(q32 + (size_t)b * HID);
    for (int i = tid; i < 256; i += 512) *(float4*)(qs + 4 * i) = qrow[i];
    __syncthreads();

    for (int s = wid; s < 64; s += 16) {
        const float4* crow = (const float4*)(ctxA + ((size_t)((b << 6) + s)) * HID);
        float acc = 0.f;
#pragma unroll 2
        for (int e = lane; e < 256; e += 32) {
            float4 a = crow[e];
            float4 qv = *(const float4*)(qs + 4 * e);
            acc += a.x * qv.x + a.y * qv.y + a.z * qv.z + a.w * qv.w;
        }
        for (int o = 16; o; o >>= 1) acc += __shfl_xor_sync(0xffffffffu, acc, o);
        if (!lane) sc[s] = acc;
    }
    __syncthreads();
    if (tid < 32) {
        float s0 = sc[tid], s1 = sc[tid + 32];
        float m = fmaxf(s0, s1);
        for (int o = 16; o; o >>= 1) m = fmaxf(m, __shfl_xor_sync(0xffffffffu, m, o));
        float e0 = expf(s0 - m), e1 = expf(s1 - m);
        float sum = e0 + e1;
        for (int o = 16; o; o >>= 1) sum += __shfl_xor_sync(0xffffffffu, sum, o);
        float inv = 1.f / sum;
        float p0 = e0 * inv, p1 = e1 * inv;
        sc[tid] = p0; sc[tid + 32] = p1;
        astd[(b << 6) + tid] = p0;
        astd[(b << 6) + tid + 32] = p1;
    }
    __syncthreads();
    const __half2* cb = (const __half2*)(ctxh + (size_t)b * 65536);
    __half2* wrow = (__half2*)(wctx + b * 2048);
    for (int e = tid; e < 512; e += 512) {
        float ax = 0.f, ay = 0.f;
#pragma unroll 8
        for (int s = 0; s < 64; s++) {
            float p = sc[s];
            float2 v = __half22float2(cb[s * 512 + e]);
            ax += p * v.x; ay += p * v.y;
        }
        wrow[e] = __floats2half2_rn(ax, ay);
    }
}

__global__ void __launch_bounds__(512) attn_copy_kernel(
    const float* __restrict__ q32,    // outputs[t] slot (B,H) fp32
    const float* __restrict__ ctxC,   // (B,S,H) fp32
    float* __restrict__ acopy,        // + t*B*S
    const __half* __restrict__ o16,   // attention out fp16, stride 1024
    const __half* __restrict__ embT,  // embAll + tn*B*E
    const __half* __restrict__ h0f,   // x1cur, stride 2048, offset 0
    __half* __restrict__ x0)
{
    int b = blockIdx.x, tid = threadIdx.x, lane = tid & 31, wid = tid >> 5;
    __shared__ float sc[64];
    __shared__ __align__(16) float qs[1024];
    const float4* qrow = (const float4*)(q32 + (size_t)b * HID);
    for (int i = tid; i < 256; i += 512) *(float4*)(qs + 4 * i) = qrow[i];
    __syncthreads();

    for (int s = wid; s < 64; s += 16) {
        const float4* crow = (const float4*)(ctxC + ((size_t)((b << 6) + s)) * HID);
        float acc = 0.f;
#pragma unroll 2
        for (int e = lane; e < 256; e += 32) {
            float4 a = crow[e];
            float4 qv = *(const float4*)(qs + 4 * e);
            acc += a.x * qv.x + a.y * qv.y + a.z * qv.z + a.w * qv.w;
        }
        for (int o = 16; o; o >>= 1) acc += __shfl_xor_sync(0xffffffffu, acc, o);
        if (!lane) sc[s] = acc;
    }
    __syncthreads();
    if (tid < 32) {
        float s0 = sc[tid], s1 = sc[tid + 32];
        float m = fmaxf(s0, s1);
        for (int o = 16; o; o >>= 1) m = fmaxf(m, __shfl_xor_sync(0xffffffffu, m, o));
        float e0 = expf(s0 - m), e1 = expf(s1 - m);
        float sum = e0 + e1;
        for (int o = 16; o; o >>= 1) sum += __shfl_xor_sync(0xffffffffu, sum, o);
        float inv = 1.f / sum;
        acopy[(b << 6) + tid] = e0 * inv;
        acopy[(b << 6) + tid + 32] = e1 * inv;
    }
    // build next step's x0 = [emb(t+1) | out_feed | h0_new]
    __half2* xr = (__half2*)(x0 + b * 2560);
    const __half2* er = (const __half2*)(embT + b * EMBD);
    for (int i = tid; i < 256; i += 512) xr[i] = er[i];
    for (int i = tid; i < 512; i += 512) {
        xr[256 + i] = ((const __half2*)(o16 + b * 1024))[i];
        xr[768 + i] = ((const __half2*)(h0f + b * 2048))[i];
    }
}

// ---------------------------------------------------------------------------
// Launch. Order matters for ncu (-s 5): launch #5 is the step-0 L0 gate GEMM.
// ---------------------------------------------------------------------------
extern "C" void kernel_launch(void* const* d_in, const int* in_sizes, int n_in,
                              void* d_out, int out_size) {
    const int*   input   = (const int*)d_in[0];
    const float* h0      = (const float*)d_in[1];
    const float* c0      = (const float*)d_in[2];
    const float* context = (const float*)d_in[3];
    const float* init_o  = (const float*)d_in[4];
    const float* emb     = (const float*)d_in[5];
    const float* Wih0    = (const float*)d_in[6];
    const float* Whh0    = (const float*)d_in[7];
    const float* b0      = (const float*)d_in[8];
    const float* Wih1    = (const float*)d_in[9];
    const float* Whh1    = (const float*)d_in[10];
    const float* b1      = (const float*)d_in[11];
    const float* ain     = (const float*)d_in[12];
    const float* aout    = (const float*)d_in[13];
    const float* cin     = (const float*)d_in[14];
    float* out = (float*)d_out;

    __half *Wcat0, *Wcat1, *Wao, *ainT, *cinT, *ctxh, *embA;
    float *ctxA, *ctxC, *ppart;
    __half *x0, *x1a, *x1b, *xattn, *o16;
    cudaGetSymbolAddress((void**)&Wcat0, g_Wcat0);
    cudaGetSymbolAddress((void**)&Wcat1, g_Wcat1);
    cudaGetSymbolAddress((void**)&Wao, g_Wao);
    cudaGetSymbolAddress((void**)&ainT, g_attn_inT);
    cudaGetSymbolAddress((void**)&cinT, g_copy_inT);
    cudaGetSymbolAddress((void**)&ctxh, g_ctxh);
    cudaGetSymbolAddress((void**)&ctxA, g_ctxA);
    cudaGetSymbolAddress((void**)&ctxC, g_ctxC);
    cudaGetSymbolAddress((void**)&embA, g_embAll);
    cudaGetSymbolAddress((void**)&x0, g_x0);
    cudaGetSymbolAddress((void**)&x1a, g_x1a);
    cudaGetSymbolAddress((void**)&x1b, g_x1b);
    cudaGetSymbolAddress((void**)&xattn, g_xattn);
    cudaGetSymbolAddress((void**)&o16, g_outf16);
    cudaGetSymbolAddress((void**)&ppart, g_projpart);

    // Launches 0..4: the minimum prerequisites of the step-0 L0 gate GEMM
    k_conv_gates<<<2048, 256>>>(Wih0, Whh0, Wcat0, 1536, 2560);   // #0
    k_conv_gates<<<2048, 256>>>(Wih1, Whh1, Wcat1, 1024, 2048);   // #1
    k_copy_c<<<256, 256>>>(c0, out + OUT_C);                      // #2
    k_init<<<64, 256>>>(input, emb, init_o, h0, x0, x1a);         // #3
    k_emb_all<<<512, 256>>>(input, emb, embA);                    // #4

    // #5: step-0 layer-0 gate GEMM  (this is the launch ncu profiles)
    gemm_kernel<32, 0><<<dim3(128, 1), 256>>>(x0, 2560, Wcat0, 2560, 2560,
        b0, out + OUT_C, out + OUT_H, x1a, nullptr, nullptr, nullptr);

    // Remaining setup (stream order keeps all dependencies satisfied)
    k_conv_plain<<<1024, 256>>>(aout, Wao, 1024 * 2048);
    k_conv_T<<<512, 256>>>(ain, ainT);
    k_conv_T<<<512, 256>>>(cin, cinT);
    k_conv_ctx<<<2048, 256>>>(context, ctxh);
    gemm_kernel<64, 2><<<dim3(16, 64), 256>>>(ctxh, 1024, ainT, 1024, 1024,
        nullptr, nullptr, nullptr, nullptr, nullptr, ctxA, nullptr);
    gemm_kernel<64, 2><<<dim3(16, 64), 256>>>(ctxh, 1024, cinT, 1024, 1024,
        nullptr, nullptr, nullptr, nullptr, nullptr, ctxC, nullptr);

    for (int t = 0; t < T_STEPS; t++) {
        __half* x1cur = (t & 1) ? x1b : x1a;
        __half* x1nxt = (t & 1) ? x1a : x1b;

        // Layer 0 gates + LSTM pointwise (h0_new -> x1cur[:,0:1024])
        if (t > 0) {  // t==0 already launched above as #5
            gemm_kernel<32, 0><<<dim3(128, 1), 256>>>(x0, 2560, Wcat0, 2560, 2560,
                b0, out + OUT_C, out + OUT_H, x1cur, nullptr, nullptr, nullptr);
        }

        // Layer 1 gates + pointwise (h1_new -> xattn[:,1024:], x1nxt[:,1024:], h_T[1] fp32)
        gemm_kernel<32, 0><<<dim3(128, 1), 256>>>(x1cur, 2048, Wcat1, 2048, 2048,
            b1, out + OUT_C + BATCH * HID, out + OUT_H + BATCH * HID,
            xattn + 1024, x1nxt + 1024, nullptr, nullptr);

        // Standard attention: fp32 scores(h1, ctxA) -> softmax -> attn_std, wctx
        attn_std_kernel<<<64, 512>>>(out + OUT_H + BATCH * HID, ctxA, ctxh,
            out + OUT_ASTD + t * BATCH * SRC, xattn);

        // Out-projection split-K: partials then tanh-reduce (fp32 outputs[t] + fp16 o16)
        gemm_kernel<32, 3><<<dim3(32, 2), 256>>>(xattn, 2048, Wao, 2048, 1024,
            nullptr, nullptr, nullptr, nullptr, nullptr, ppart, nullptr);
        k_proj_epi<<<256, 256>>>(ppart, out + (size_t)t * BATCH * HID, o16);

        // Copy attention (fp32 scores) + build x0 for next step
        int tn = (t + 1 < T_STEPS) ? t + 1 : T_STEPS - 1;
        attn_copy_kernel<<<64, 512>>>(out + (size_t)t * BATCH * HID, ctxC,
            out + OUT_ACOPY + t * BATCH * SRC,
            o16, embA + (size_t)tn * BATCH * EMBD, x1cur, x0);
    }
}